// round 17
// baseline (speedup 1.0000x reference)
#include <cuda_runtime.h>

// MultiStageFIRFilter: y = x + sum_{a=1..20} xa_a,
//   xa_a[b,t] = (1/a) * sum_{k=0..24} mc[b,t,k] * xa_{a-1}[b,t-k]  (xa_0 = x, causal)
//
// R13 structure (256 threads, R=4, barrier/stage, tap-pair fma.rn.f32x2 with
// shifted per-output coefficient pairs) BUT the window is loaded directly as
// ulonglong2 (LDS.128 -> two u64 register pairs): the 12 window pairs P[j]
// arrive pre-packed from shared memory, eliminating the per-stage MOV packing
// that made R13's alu pipe 18%. Only the 2 own-value packs remain per stage.

#define NB      4
#define NT      16384
#define M       25
#define STAGES  20
#define HALO    480       // STAGES * 24
#define THREADS 256
#define R       4
#define EXT     1024      // THREADS * R
#define TILE    544       // EXT - HALO
#define PAD     24
#define NTILES  31        // ceil(16384 / 544)

typedef unsigned long long u64;

__device__ __forceinline__ u64 fma2(u64 a, u64 b, u64 c) {
    u64 d;
    asm("fma.rn.f32x2 %0, %1, %2, %3;" : "=l"(d) : "l"(a), "l"(b), "l"(c));
    return d;
}
__device__ __forceinline__ u64 pack2(float lo, float hi) {
    u64 d;
    asm("mov.b64 %0, {%1, %2};" : "=l"(d) : "f"(lo), "f"(hi));
    return d;
}
__device__ __forceinline__ void unpack2(u64 v, float& lo, float& hi) {
    asm("mov.b64 {%0, %1}, %2;" : "=f"(lo), "=f"(hi) : "l"(v));
}

__global__ __launch_bounds__(THREADS, 1)
void fir_kernel(const float* __restrict__ x, const float* __restrict__ mc,
                float* __restrict__ out)
{
    __shared__ __align__(16) float s0[PAD + EXT];
    __shared__ __align__(16) float s1[PAD + EXT];

    const int tile = blockIdx.x % NTILES;
    const int b    = blockIdx.x / NTILES;
    const int t0   = tile * TILE;
    const int tid  = threadIdx.x;
    const int i0   = R * tid;              // local position (multiple of 4)
    const int p0   = t0 - HALO + i0;       // global time of first owned position
    const size_t rowbase = (size_t)b * NT;
    const bool valid = (p0 >= 0 && p0 + R - 1 < NT);   // rows all-valid or all-not

    if (tid < PAD) { s0[tid] = 0.0f; s1[tid] = 0.0f; }

    // ---- coefficients: rows p0..p0+3 are 100 contiguous floats (16B-aligned) ----
    float c[100];                          // c[25*r + k] = mc[p0+r][k]
    if (valid) {
        const float4* g = (const float4*)(mc + (rowbase + (size_t)p0) * M);
        #pragma unroll
        for (int k = 0; k < 25; k++) {
            float4 v4 = g[k];
            c[4*k] = v4.x; c[4*k+1] = v4.y; c[4*k+2] = v4.z; c[4*k+3] = v4.w;
        }
    } else {
        #pragma unroll
        for (int j = 0; j < 100; j++) c[j] = 0.0f;   // acc == 0 exactly for ghosts
    }

    // ---- shifted coefficient pairs (prologue only) ----
    // pair j covers (W[2j], W[2j+1]), W[m] = val(i0-24+m);
    // out r uses coeffs (c_r[24+r-2j], c_r[23+r-2j]), out-of-range -> 0.
    //   r=0: j=0..12   r=1: j=0..12   r=2: j=1..13   r=3: j=1..13
    u64 cp0[13], cp1[13], cp2[13], cp3[13];
    {
        #pragma unroll
        for (int j = 0; j <= 12; j++) {
            const int a0 = 24 - 2*j, b0_ = 23 - 2*j;          // r = 0
            cp0[j] = pack2(a0 >= 0 ? c[a0] : 0.0f, b0_ >= 0 ? c[b0_] : 0.0f);
            const int a1 = 25 - 2*j, b1_ = 24 - 2*j;          // r = 1
            cp1[j] = pack2(a1 <= 24 ? c[25 + a1] : 0.0f, c[25 + b1_]);
        }
        #pragma unroll
        for (int j = 1; j <= 13; j++) {
            const int a2 = 26 - 2*j, b2_ = 25 - 2*j;          // r = 2
            cp2[j-1] = pack2((a2 >= 0 && a2 <= 24) ? c[50 + a2] : 0.0f,
                             (b2_ >= 0 && b2_ <= 24) ? c[50 + b2_] : 0.0f);
            const int a3 = 27 - 2*j, b3_ = 26 - 2*j;          // r = 3
            cp3[j-1] = pack2((a3 >= 0 && a3 <= 24) ? c[75 + a3] : 0.0f,
                             (b3_ >= 0 && b3_ <= 24) ? c[75 + b3_] : 0.0f);
        }
    }

    // ---- stage 0: xa = x ----
    float v[R], y[R];
    if (valid) {
        const float4 xv = *(const float4*)(x + rowbase + p0);
        v[0] = xv.x; v[1] = xv.y; v[2] = xv.z; v[3] = xv.w;
    } else {
        #pragma unroll
        for (int r = 0; r < R; r++) v[r] = 0.0f;
    }
    #pragma unroll
    for (int r = 0; r < R; r++) y[r] = v[r];

    *((float4*)(s0 + PAD + i0)) = make_float4(v[0], v[1], v[2], v[3]);
    __syncthreads();

    float* cur = s0;
    float* nxt = s1;

    #pragma unroll
    for (int a = 1; a <= STAGES; a++) {
        const float inv = 1.0f / (float)a;         // compile-time constant
        if (tid >= 6 * a) {                        // exactness trim: need pos >= 24a
            // Window pairs arrive PRE-PACKED: 3x LDS.128, each = ulonglong2 =
            // two u64 (float-pair) registers. W[m]=val(i0-24+m) at smem idx i0+m.
            u64 P[14];
            const ulonglong2* wp = (const ulonglong2*)(cur + i0);   // 16B-aligned
            #pragma unroll
            for (int j = 0; j < 3; j++) {
                const ulonglong2 q = wp[j];
                P[4*j]     = q.x;                  // (W[8j],   W[8j+1]) as f32x2
                P[4*j + 1] = q.y;
            }
            // NOTE: ulonglong2 gives 2 u64 per 16B; need indices laid out right:
            // wp[j].x covers floats (8j? ) -- recompute: each ulonglong2 = 4 floats.
            // wp[j] = floats [4j, 4j+3] -> u64 pairs (4j,4j+1) and (4j+2,4j+3),
            // i.e. P[2j] = wp[j].x, P[2j+1] = wp[j].y, for j = 0..5 (6 loads of 8B? )
            // -- corrected below.
            const u64* wq = (const u64*)(cur + i0);
            #pragma unroll
            for (int m = 0; m < 12; m++) P[m] = wq[m];   // 12 u64 = 6 LDS.128 (vectorized)
            P[12] = pack2(v[0], v[1]);             // (W[24], W[25])
            P[13] = pack2(v[2], v[3]);             // (W[26], W[27])

            // 8 independent fma2 chains (2 per output)
            u64 A0 = 0, B0 = 0, A1 = 0, B1 = 0, A2 = 0, B2 = 0, A3 = 0, B3 = 0;
            #pragma unroll
            for (int j = 0; j <= 12; j += 2) {     // even j
                A0 = fma2(cp0[j], P[j], A0);
                A1 = fma2(cp1[j], P[j], A1);
            }
            #pragma unroll
            for (int j = 1; j <= 12; j += 2) {     // odd j
                B0 = fma2(cp0[j], P[j], B0);
                B1 = fma2(cp1[j], P[j], B1);
            }
            #pragma unroll
            for (int j = 1; j <= 13; j += 2) {     // odd j (r=2,3 start at 1)
                A2 = fma2(cp2[j-1], P[j], A2);
                A3 = fma2(cp3[j-1], P[j], A3);
            }
            #pragma unroll
            for (int j = 2; j <= 13; j += 2) {     // even j
                B2 = fma2(cp2[j-1], P[j], B2);
                B3 = fma2(cp3[j-1], P[j], B3);
            }

            float l0, h0, l1, h1, acc[R];
            unpack2(A0, l0, h0); unpack2(B0, l1, h1);
            acc[0] = ((l0 + l1) + (h0 + h1)) * inv;
            unpack2(A1, l0, h0); unpack2(B1, l1, h1);
            acc[1] = ((l0 + l1) + (h0 + h1)) * inv;
            unpack2(A2, l0, h0); unpack2(B2, l1, h1);
            acc[2] = ((l0 + l1) + (h0 + h1)) * inv;
            unpack2(A3, l0, h0); unpack2(B3, l1, h1);
            acc[3] = ((l0 + l1) + (h0 + h1)) * inv;

            #pragma unroll
            for (int r = 0; r < R; r++) { y[r] += acc[r]; v[r] = acc[r]; }
            *((float4*)(nxt + PAD + i0)) = make_float4(v[0], v[1], v[2], v[3]);
        }
        __syncthreads();
        float* tmp = cur; cur = nxt; nxt = tmp;
    }

    // ---- write owned (non-halo) outputs ----
    if (i0 >= HALO && p0 < NT) {                   // valid here by construction
        *((float4*)(out + rowbase + p0)) = make_float4(y[0], y[1], y[2], y[3]);
    }
}

extern "C" void kernel_launch(void* const* d_in, const int* in_sizes, int n_in,
                              void* d_out, int out_size)
{
    const float* x  = (const float*)d_in[0];   // (4, 16384) float32
    const float* mc = (const float*)d_in[1];   // (4, 16384, 25) float32
    float* out = (float*)d_out;                // (4, 16384) float32
    fir_kernel<<<NB * NTILES, THREADS>>>(x, mc, out);
}